// round 11
// baseline (speedup 1.0000x reference)
#include <cuda_runtime.h>
#include <cstdint>

#define BATCH 4
#define SEQLEN 4096
#define DMODEL 1024
#define DSTATE 16
#define NROWS (BATCH*SEQLEN)
#define NCHUNK 256                // 16-row chunks per sequence

// Scratch in [b][s][n] layout
__device__ float g_bx[NROWS*DSTATE];
__device__ float g_decay[NROWS*DSTATE];
__device__ float g_cA[BATCH*DSTATE*NCHUNK];
__device__ float g_cH[BATCH*DSTATE*NCHUNK];
__device__ float g_hpre[BATCH*DSTATE*NCHUNK];

// ---- packed f32x2 helpers ---------------------------------------------------
__device__ __forceinline__ double pk2(float lo, float hi) {
    double d; asm("mov.b64 %0, {%1, %2};" : "=d"(d) : "f"(lo), "f"(hi)); return d;
}
__device__ __forceinline__ double fma2(double a, double b, double c) {
    double d; asm("fma.rn.f32x2 %0, %1, %2, %3;" : "=d"(d) : "d"(a), "d"(b), "d"(c)); return d;
}
__device__ __forceinline__ double mul2(double a, double b) {
    double d; asm("mul.rn.f32x2 %0, %1, %2;" : "=d"(d) : "d"(a), "d"(b)); return d;
}
__device__ __forceinline__ double add2(double a, double b) {
    double d; asm("add.rn.f32x2 %0, %1, %2;" : "=d"(d) : "d"(a), "d"(b)); return d;
}
__device__ __forceinline__ float lo2(double d) { return __int_as_float(__double2loint(d)); }
__device__ __forceinline__ float hi2(double d) { return __int_as_float(__double2hiint(d)); }
__device__ __forceinline__ void stcs2(void* p, double a, double b) {
    asm volatile("st.global.cs.v2.f64 [%0], {%1, %2};" :: "l"(p), "d"(a), "d"(b) : "memory");
}

#define XSLAB 1065                 // per-warp x slab stride (32*33 + 9)

// ---------------------------------------------------------------------------
// Kernel 1: Bx = x @ B_in ; decay = exp(softplus(Bx) * -exp(A))
// LANE = ROW design. 512 blocks x 32 rows, 128 threads (4 warps).
// Warp w owns e-slice [w*256, +256) in 8 stages of 32 e. Per e-step:
//   x from transposed smem tile (pitch 33, conflict-free, 4B/lane)
//   B[e][0..16) broadcast LDS (counts once) -> 8 FFMA2 into acc[8].
// LDS traffic ~0.375 B/FMA (vs 1.0 before). Double-buffered stages.
// 4-way cross-warp reduce via smem, then epilogue as before.
// ---------------------------------------------------------------------------
__global__ __launch_bounds__(128) void bx_kernel(const float* __restrict__ x,
                                                 const float* __restrict__ A,
                                                 const float* __restrict__ B_in) {
    __shared__ __align__(16) float sxf[2][4 * XSLAB + 7];  // x, [buf][w*XSLAB + ei*33 + row]
    __shared__ __align__(16) float sbq[2][4][32][16];      // B, [buf][w][ei][s]
    __shared__ __align__(16) double sdump[4][8][32];       // partials [w][j][row]
    __shared__ float sdec[DSTATE][33];
    __shared__ float sbxs[DSTATE][33];

    const int t = threadIdx.x;
    const int wid = t >> 5, lane = t & 31;
    const int row0 = blockIdx.x * 32;
    const int r_ld = t >> 2;                   // staging row 0..31
    const int sub = t & 3;

    double acc[8];
#pragma unroll
    for (int j = 0; j < 8; j++) acc[j] = 0.0;

    float4 xr[8], br[4];

    // ---- stage 0 load ----
#pragma unroll
    for (int i = 0; i < 8; i++) {
        const int f = sub * 8 + i, w = f >> 3, e4 = f & 7;
        xr[i] = *(const float4*)(x + (size_t)(row0 + r_ld) * DMODEL + w * 256 + e4 * 4);
    }
#pragma unroll
    for (int i = 0; i < 4; i++) {
        const int idx = i * 128 + t;
        const int lw = idx >> 7, rest = idx & 127, ei = rest >> 2, u = rest & 3;
        br[i] = ((const float4*)B_in)[(size_t)(lw * 256 + ei) * 4 + u];
    }
#pragma unroll
    for (int i = 0; i < 8; i++) {
        const int f = sub * 8 + i, w = f >> 3, e4 = f & 7;
        float* base = &sxf[0][w * XSLAB + (e4 * 4) * 33 + r_ld];
        base[0] = xr[i].x; base[33] = xr[i].y; base[66] = xr[i].z; base[99] = xr[i].w;
    }
#pragma unroll
    for (int i = 0; i < 4; i++) {
        const int idx = i * 128 + t;
        const int lw = idx >> 7, rest = idx & 127, ei = rest >> 2, u = rest & 3;
        *(float4*)&sbq[0][lw][ei][u * 4] = br[i];
    }
    __syncthreads();

    for (int st = 0; st < 8; st++) {
        // issue next-stage loads early (overlap with compute)
        if (st < 7) {
#pragma unroll
            for (int i = 0; i < 8; i++) {
                const int f = sub * 8 + i, w = f >> 3, e4 = f & 7;
                xr[i] = *(const float4*)(x + (size_t)(row0 + r_ld) * DMODEL
                                         + w * 256 + (st + 1) * 32 + e4 * 4);
            }
#pragma unroll
            for (int i = 0; i < 4; i++) {
                const int idx = i * 128 + t;
                const int lw = idx >> 7, rest = idx & 127, ei = rest >> 2, u = rest & 3;
                br[i] = ((const float4*)B_in)[(size_t)(lw * 256 + (st + 1) * 32 + ei) * 4 + u];
            }
        }

        // compute this stage
        {
            const int buf = st & 1;
            const float* xp = &sxf[buf][wid * XSLAB + lane];
            const double2* bp = (const double2*)&sbq[buf][wid][0][0];
#pragma unroll
            for (int ei = 0; ei < 32; ei++) {
                const float xv = xp[ei * 33];
                const double xx = pk2(xv, xv);
                const double2 b0 = bp[ei * 4 + 0];
                const double2 b1 = bp[ei * 4 + 1];
                const double2 b2 = bp[ei * 4 + 2];
                const double2 b3 = bp[ei * 4 + 3];
                acc[0] = fma2(xx, b0.x, acc[0]);
                acc[1] = fma2(xx, b0.y, acc[1]);
                acc[2] = fma2(xx, b1.x, acc[2]);
                acc[3] = fma2(xx, b1.y, acc[3]);
                acc[4] = fma2(xx, b2.x, acc[4]);
                acc[5] = fma2(xx, b2.y, acc[5]);
                acc[6] = fma2(xx, b3.x, acc[6]);
                acc[7] = fma2(xx, b3.y, acc[7]);
            }
        }

        if (st < 7) {
            __syncthreads();
            const int nbuf = (st + 1) & 1;
#pragma unroll
            for (int i = 0; i < 8; i++) {
                const int f = sub * 8 + i, w = f >> 3, e4 = f & 7;
                float* base = &sxf[nbuf][w * XSLAB + (e4 * 4) * 33 + r_ld];
                base[0] = xr[i].x; base[33] = xr[i].y; base[66] = xr[i].z; base[99] = xr[i].w;
            }
#pragma unroll
            for (int i = 0; i < 4; i++) {
                const int idx = i * 128 + t;
                const int lw = idx >> 7, rest = idx & 127, ei = rest >> 2, u = rest & 3;
                *(float4*)&sbq[nbuf][lw][ei][u * 4] = br[i];
            }
            __syncthreads();
        }
    }

    // dump partials: sdump[w][j][row]
#pragma unroll
    for (int j = 0; j < 8; j++) sdump[wid][j][lane] = acc[j];
    __syncthreads();

    // 4-way reduce + softplus/exp: 256 items (32 rows x 8 pairs), 2/thread
#pragma unroll
    for (int ii = 0; ii < 2; ii++) {
        const int idx = ii * 128 + t;
        const int j = idx >> 5, rl = idx & 31;
        const double v = add2(add2(sdump[0][j][rl], sdump[1][j][rl]),
                              add2(sdump[2][j][rl], sdump[3][j][rl]));
        const float bx0 = lo2(v), bx1 = hi2(v);
        const int s0 = 2 * j;
        const float an0 = -expf(A[s0]);
        const float an1 = -expf(A[s0 + 1]);
        const float sp0 = (bx0 > 20.f) ? bx0 : log1pf(expf(bx0));
        const float sp1 = (bx1 > 20.f) ? bx1 : log1pf(expf(bx1));
        sdec[s0][rl] = expf(sp0 * an0);
        sdec[s0 + 1][rl] = expf(sp1 * an1);
        sbxs[s0][rl] = bx0;
        sbxs[s0 + 1][rl] = bx1;
    }
    __syncthreads();

    const int b = row0 >> 12;
    const int n0 = row0 & (SEQLEN - 1);
    // coalesced global writes in [b][s][n]
#pragma unroll
    for (int i = 0; i < 4; i++) {
        const int idx = i * 128 + t;               // 0..511 (16 s x 32 n)
        const int s = idx >> 5, j = idx & 31;
        const size_t o = ((size_t)(b * DSTATE + s)) * SEQLEN + n0 + j;
        g_bx[o] = sbxs[s][j];
        g_decay[o] = sdec[s][j];
    }
    // two 16-row chunk summaries per block
    if (t < 32) {
        const int s = t & 15, half = t >> 4;
        float a = 1.f, h = 0.f;
#pragma unroll
        for (int j = 0; j < 16; j++) {
            const int jj = half * 16 + j;
            const float d = sdec[s][jj];
            h = fmaf(h, d, sbxs[s][jj]);
            a *= d;
        }
        const int so = (b * DSTATE + s) * NCHUNK + (n0 >> 4) + half;
        g_cA[so] = a;
        g_cH[so] = h;
    }
}

// ---------------------------------------------------------------------------
// Kernel 2: scan 256 chunk summaries per (b,s); write EXCLUSIVE prefix.
// ---------------------------------------------------------------------------
__global__ __launch_bounds__(256) void chunkscan_kernel() {
    __shared__ float sA[256], sH[256];
    const int t = threadIdx.x;
    const int seq = blockIdx.x;                    // b*16 + s
    float a = g_cA[seq * NCHUNK + t];
    float h = g_cH[seq * NCHUNK + t];
    sA[t] = a; sH[t] = h;
    __syncthreads();
#pragma unroll
    for (int off = 1; off < 256; off <<= 1) {
        float pa = 1.f, ph = 0.f;
        const bool act = (t >= off);
        if (act) { pa = sA[t - off]; ph = sH[t - off]; }
        __syncthreads();
        if (act) {
            h = fmaf(a, ph, h);
            a = a * pa;
            sA[t] = a; sH[t] = h;
        }
        __syncthreads();
    }
    g_hpre[seq * NCHUNK + t] = (t == 0) ? 0.f : sH[t - 1];
}

// ---------------------------------------------------------------------------
// Kernel 3: replay 16-row chunk + y = hs@C + x*D.
// 2048 blocks x (16 rows x 512 cols), 128 threads; thread owns 4 cols.
// Even/odd split accumulators halve the FFMA2 dependency chain.
// x loaded only if this thread's D slice is nonzero.
// ---------------------------------------------------------------------------
__global__ __launch_bounds__(128, 4) void out_kernel(const float* __restrict__ x,
                                                     const float* __restrict__ C,
                                                     const float* __restrict__ D,
                                                     float* __restrict__ y) {
    __shared__ float sd[DSTATE][17], sv[DSTATE][17];
    __shared__ __align__(16) double hd[16][16];    // (h,h) pairs, [row][s]
    const int t = threadIdx.x;
    const int rb = blockIdx.x >> 1;
    const int half = blockIdx.x & 1;
    const int row0 = rb * 16;
    const int b = rb >> 8, n0 = row0 & (SEQLEN - 1);
    const int chunk = rb & 255;
    const int c0 = half * 512 + 4 * t;

    // stage decay/bx tiles [16 s][16 n]
#pragma unroll
    for (int i = 0; i < 2; i++) {
        const int idx = i * 128 + t;
        const int s = idx >> 4, j = idx & 15;
        const size_t o = ((size_t)(b * DSTATE + s)) * SEQLEN + n0 + j;
        sd[s][j] = g_decay[o];
        sv[s][j] = g_bx[o];
    }
    __syncthreads();

    // replay this 16-row chunk from the precomputed exclusive prefix
    if (t < DSTATE) {
        float h = g_hpre[(b * DSTATE + t) * NCHUNK + chunk];
#pragma unroll
        for (int j = 0; j < 16; j++) {
            h = fmaf(h, sd[t][j], sv[t][j]);
            hd[j][t] = pk2(h, h);
        }
    }
    __syncthreads();

    // C columns [c0, c0+4) as natural packed doubles
    double cd0[16], cd1[16];
#pragma unroll
    for (int s = 0; s < 16; s++) {
        const double2 cv = *(const double2*)(C + (size_t)s * DMODEL + c0);
        cd0[s] = cv.x;
        cd1[s] = cv.y;
    }
    const float4 dv = *(const float4*)(D + c0);
    const bool needx = (dv.x != 0.f) || (dv.y != 0.f) || (dv.z != 0.f) || (dv.w != 0.f);
    const double dd0 = pk2(dv.x, dv.y), dd1 = pk2(dv.z, dv.w);

    const float* xrow = x + (size_t)row0 * DMODEL + c0;
    float* yrow = y + (size_t)row0 * DMODEL + c0;

    double2 nx[4];
    if (needx) {
#pragma unroll
        for (int i = 0; i < 4; i++)
            nx[i] = *(const double2*)(xrow + (size_t)i * DMODEL);
    }

#pragma unroll
    for (int r = 0; r < 16; r++) {
        double a0e, a1e;
        double a0o = 0.0, a1o = 0.0;
        if (needx) {
            const double2 cx = nx[r & 3];
            if (r + 4 < 16)
                nx[r & 3] = *(const double2*)(xrow + (size_t)(r + 4) * DMODEL);
            a0e = mul2(cx.x, dd0);
            a1e = mul2(cx.y, dd1);
        } else {
            a0e = 0.0; a1e = 0.0;
        }
#pragma unroll
        for (int q = 0; q < 4; q++) {
            const double2 h2a = *(const double2*)&hd[r][4 * q];
            const double2 h2b = *(const double2*)&hd[r][4 * q + 2];
            a0e = fma2(h2a.x, cd0[4 * q], a0e);
            a1e = fma2(h2a.x, cd1[4 * q], a1e);
            a0o = fma2(h2a.y, cd0[4 * q + 1], a0o);
            a1o = fma2(h2a.y, cd1[4 * q + 1], a1o);
            a0e = fma2(h2b.x, cd0[4 * q + 2], a0e);
            a1e = fma2(h2b.x, cd1[4 * q + 2], a1e);
            a0o = fma2(h2b.y, cd0[4 * q + 3], a0o);
            a1o = fma2(h2b.y, cd1[4 * q + 3], a1o);
        }
        stcs2(yrow + (size_t)r * DMODEL, add2(a0e, a0o), add2(a1e, a1o));
    }
}

extern "C" void kernel_launch(void* const* d_in, const int* in_sizes, int n_in,
                              void* d_out, int out_size) {
    const float* x    = (const float*)d_in[0];   // [4,4096,1024]
    const float* A    = (const float*)d_in[1];   // [1,16]
    const float* B_in = (const float*)d_in[2];   // [1024,16]
    const float* C    = (const float*)d_in[3];   // [16,1024]
    const float* D    = (const float*)d_in[4];   // [1024]
    float* y = (float*)d_out;                    // [4,4096,1024]

    bx_kernel<<<512, 128>>>(x, A, B_in);
    chunkscan_kernel<<<64, 256>>>();
    out_kernel<<<2048, 128>>>(x, C, D, y);
}

// round 12
// speedup vs baseline: 1.4541x; 1.4541x over previous
#include <cuda_runtime.h>
#include <cstdint>

#define BATCH 4
#define SEQLEN 4096
#define DMODEL 1024
#define DSTATE 16
#define NROWS (BATCH*SEQLEN)
#define NCHUNK 256                // 16-row chunks per sequence

// Scratch in [b][s][n] layout
__device__ float g_bx[NROWS*DSTATE];
__device__ float g_decay[NROWS*DSTATE];
__device__ float g_cA[BATCH*DSTATE*NCHUNK];
__device__ float g_cH[BATCH*DSTATE*NCHUNK];
__device__ float g_hpre[BATCH*DSTATE*NCHUNK];

// ---- packed f32x2 helpers ---------------------------------------------------
__device__ __forceinline__ double pk2(float lo, float hi) {
    double d; asm("mov.b64 %0, {%1, %2};" : "=d"(d) : "f"(lo), "f"(hi)); return d;
}
__device__ __forceinline__ double fma2(double a, double b, double c) {
    double d; asm("fma.rn.f32x2 %0, %1, %2, %3;" : "=d"(d) : "d"(a), "d"(b), "d"(c)); return d;
}
__device__ __forceinline__ double mul2(double a, double b) {
    double d; asm("mul.rn.f32x2 %0, %1, %2;" : "=d"(d) : "d"(a), "d"(b)); return d;
}
__device__ __forceinline__ double add2(double a, double b) {
    double d; asm("add.rn.f32x2 %0, %1, %2;" : "=d"(d) : "d"(a), "d"(b)); return d;
}
__device__ __forceinline__ float lo2(double d) { return __int_as_float(__double2loint(d)); }
__device__ __forceinline__ float hi2(double d) { return __int_as_float(__double2hiint(d)); }
__device__ __forceinline__ void stcs2(void* p, double a, double b) {
    asm volatile("st.global.cs.v2.f64 [%0], {%1, %2};" :: "l"(p), "d"(a), "d"(b) : "memory");
}

// ---------------------------------------------------------------------------
// Kernel 1: Bx = x @ B_in ; decay = exp(softplus(Bx) * -exp(A))
// 512 blocks x 32 rows, 128 threads; thread (c=t&15, rgrp=t>>4) owns 4 rows,
// e-stripe e = c+16k. B staged in 2 stages of 512 rows (36 KB, pitch 18 ->
// conflict-free LDS.64). 4-deep x prefetch (16 outstanding LDG/thread) so
// loads are issued ~4 k-iters (~460+ cyc) ahead of use. bv split 4+4 to
// keep live registers under the 128 cap. Emits two 16-row chunk summaries.
// ---------------------------------------------------------------------------
__global__ __launch_bounds__(128, 4) void bx_kernel(const float* __restrict__ x,
                                                    const float* __restrict__ A,
                                                    const float* __restrict__ B_in) {
    __shared__ __align__(16) float sb[512 * 18];   // 36 KB
    __shared__ double sdump[32][8];
    __shared__ float sdec[DSTATE][33];
    __shared__ float sbxs[DSTATE][33];

    const int t = threadIdx.x;
    const int c = t & 15;
    const int rgrp = t >> 4;
    const int row0 = blockIdx.x * 32 + rgrp * 4;

    double acc[4][8];
#pragma unroll
    for (int r = 0; r < 4; r++)
#pragma unroll
        for (int j = 0; j < 8; j++) acc[r][j] = 0.0;

    for (int stage = 0; stage < 2; stage++) {
        __syncthreads();
        // stage B rows [stage*512, +512) -> sb pitch 18 (float4 gmem reads)
        const float4* bsrc = (const float4*)(B_in + (size_t)stage * 512 * DSTATE);
#pragma unroll
        for (int i = 0; i < 16; i++) {
            int idx = i * 128 + t;                 // float4 unit 0..2047
            int e = idx >> 2, u = idx & 3;
            float4 v = bsrc[idx];
            double* dst = (double*)(sb + e * 18 + u * 4);
            dst[0] = ((const double*)&v)[0];
            dst[1] = ((const double*)&v)[1];
        }
        __syncthreads();

        const float* xp = x + (size_t)row0 * DMODEL + stage * 512 + c;
        // prime 4-deep prefetch: 16 outstanding LDG.32
        float p[4][4];
#pragma unroll
        for (int pi = 0; pi < 4; pi++)
#pragma unroll
            for (int r = 0; r < 4; r++)
                p[pi][r] = xp[r * DMODEL + pi * 16];

#pragma unroll 8
        for (int k = 0; k < 32; k++) {
            float cx[4];
#pragma unroll
            for (int r = 0; r < 4; r++) cx[r] = p[k & 3][r];
            if (k < 28) {
#pragma unroll
                for (int r = 0; r < 4; r++) p[k & 3][r] = xp[r * DMODEL + (k + 4) * 16];
            }
            double xx[4];
#pragma unroll
            for (int r = 0; r < 4; r++) xx[r] = pk2(cx[r], cx[r]);

            const double* bp = (const double*)(sb + (c + 16 * k) * 18);
            // first half: bv[0..3]
            {
                double bv[4];
#pragma unroll
                for (int j = 0; j < 4; j++) bv[j] = bp[j];
#pragma unroll
                for (int r = 0; r < 4; r++)
#pragma unroll
                    for (int j = 0; j < 4; j++)
                        acc[r][j] = fma2(xx[r], bv[j], acc[r][j]);
            }
            // second half: bv[4..7]
            {
                double bv[4];
#pragma unroll
                for (int j = 0; j < 4; j++) bv[j] = bp[4 + j];
#pragma unroll
                for (int r = 0; r < 4; r++)
#pragma unroll
                    for (int j = 0; j < 4; j++)
                        acc[r][4 + j] = fma2(xx[r], bv[j], acc[r][4 + j]);
            }
        }
    }

    // reduce across the 16 c-lanes
#pragma unroll
    for (int off = 1; off < 16; off <<= 1) {
#pragma unroll
        for (int r = 0; r < 4; r++)
#pragma unroll
            for (int j = 0; j < 8; j++) {
                double o = __shfl_xor_sync(0xffffffffu, acc[r][j], off);
                acc[r][j] = add2(acc[r][j], o);
            }
    }

    __syncthreads();
    if (c == 0) {
#pragma unroll
        for (int r = 0; r < 4; r++)
#pragma unroll
            for (int j = 0; j < 8; j++) sdump[rgrp * 4 + r][j] = acc[r][j];
    }
    __syncthreads();

    // softplus/exp: 256 items (32 rows x 8 pairs), 2 per thread
#pragma unroll
    for (int i = 0; i < 2; i++) {
        const int idx = i * 128 + t;
        const int rl = idx >> 3, q = idx & 7;
        const double v = sdump[rl][q];
        const float bx0 = lo2(v), bx1 = hi2(v);
        const int s0 = 2 * q;
        const float an0 = -expf(A[s0]);
        const float an1 = -expf(A[s0 + 1]);
        const float sp0 = (bx0 > 20.f) ? bx0 : log1pf(expf(bx0));
        const float sp1 = (bx1 > 20.f) ? bx1 : log1pf(expf(bx1));
        sdec[s0][rl] = expf(sp0 * an0);
        sdec[s0 + 1][rl] = expf(sp1 * an1);
        sbxs[s0][rl] = bx0;
        sbxs[s0 + 1][rl] = bx1;
    }
    __syncthreads();

    const int b = blockIdx.x >> 7;
    const int n0 = (blockIdx.x * 32) & (SEQLEN - 1);
    // coalesced global writes in [b][s][n]
#pragma unroll
    for (int i = 0; i < 4; i++) {
        int idx = i * 128 + t;
        int s = idx >> 5, j = idx & 31;
        size_t o = ((size_t)(b * DSTATE + s)) * SEQLEN + n0 + j;
        g_bx[o] = sbxs[s][j];
        g_decay[o] = sdec[s][j];
    }
    // two 16-row chunk summaries per block
    if (t < 32) {
        const int s = t & 15, half = t >> 4;
        float a = 1.f, h = 0.f;
#pragma unroll
        for (int j = 0; j < 16; j++) {
            const int jj = half * 16 + j;
            const float d = sdec[s][jj];
            h = fmaf(h, d, sbxs[s][jj]);
            a *= d;
        }
        const int so = (b * DSTATE + s) * NCHUNK + (blockIdx.x & 127) * 2 + half;
        g_cA[so] = a;
        g_cH[so] = h;
    }
}

// ---------------------------------------------------------------------------
// Kernel 2: scan 256 chunk summaries per (b,s); write EXCLUSIVE prefix.
// ---------------------------------------------------------------------------
__global__ __launch_bounds__(256) void chunkscan_kernel() {
    __shared__ float sA[256], sH[256];
    const int t = threadIdx.x;
    const int seq = blockIdx.x;                    // b*16 + s
    float a = g_cA[seq * NCHUNK + t];
    float h = g_cH[seq * NCHUNK + t];
    sA[t] = a; sH[t] = h;
    __syncthreads();
#pragma unroll
    for (int off = 1; off < 256; off <<= 1) {
        float pa = 1.f, ph = 0.f;
        const bool act = (t >= off);
        if (act) { pa = sA[t - off]; ph = sH[t - off]; }
        __syncthreads();
        if (act) {
            h = fmaf(a, ph, h);
            a = a * pa;
            sA[t] = a; sH[t] = h;
        }
        __syncthreads();
    }
    g_hpre[seq * NCHUNK + t] = (t == 0) ? 0.f : sH[t - 1];
}

// ---------------------------------------------------------------------------
// Kernel 3: replay 16-row chunk + y = hs@C + x*D.   (R11 version, ~19.3 us)
// 2048 blocks x (16 rows x 512 cols), 128 threads; thread owns 4 cols.
// Even/odd split accumulators halve the FFMA2 dependency chain.
// x loaded only if this thread's D slice is nonzero.
// ---------------------------------------------------------------------------
__global__ __launch_bounds__(128, 4) void out_kernel(const float* __restrict__ x,
                                                     const float* __restrict__ C,
                                                     const float* __restrict__ D,
                                                     float* __restrict__ y) {
    __shared__ float sd[DSTATE][17], sv[DSTATE][17];
    __shared__ __align__(16) double hd[16][16];    // (h,h) pairs, [row][s]
    const int t = threadIdx.x;
    const int rb = blockIdx.x >> 1;
    const int half = blockIdx.x & 1;
    const int row0 = rb * 16;
    const int b = rb >> 8, n0 = row0 & (SEQLEN - 1);
    const int chunk = rb & 255;
    const int c0 = half * 512 + 4 * t;

    // stage decay/bx tiles [16 s][16 n]
#pragma unroll
    for (int i = 0; i < 2; i++) {
        const int idx = i * 128 + t;
        const int s = idx >> 4, j = idx & 15;
        const size_t o = ((size_t)(b * DSTATE + s)) * SEQLEN + n0 + j;
        sd[s][j] = g_decay[o];
        sv[s][j] = g_bx[o];
    }
    __syncthreads();

    // replay this 16-row chunk from the precomputed exclusive prefix
    if (t < DSTATE) {
        float h = g_hpre[(b * DSTATE + t) * NCHUNK + chunk];
#pragma unroll
        for (int j = 0; j < 16; j++) {
            h = fmaf(h, sd[t][j], sv[t][j]);
            hd[j][t] = pk2(h, h);
        }
    }
    __syncthreads();

    // C columns [c0, c0+4) as natural packed doubles
    double cd0[16], cd1[16];
#pragma unroll
    for (int s = 0; s < 16; s++) {
        const double2 cv = *(const double2*)(C + (size_t)s * DMODEL + c0);
        cd0[s] = cv.x;
        cd1[s] = cv.y;
    }
    const float4 dv = *(const float4*)(D + c0);
    const bool needx = (dv.x != 0.f) || (dv.y != 0.f) || (dv.z != 0.f) || (dv.w != 0.f);
    const double dd0 = pk2(dv.x, dv.y), dd1 = pk2(dv.z, dv.w);

    const float* xrow = x + (size_t)row0 * DMODEL + c0;
    float* yrow = y + (size_t)row0 * DMODEL + c0;

    double2 nx[4];
    if (needx) {
#pragma unroll
        for (int i = 0; i < 4; i++)
            nx[i] = *(const double2*)(xrow + (size_t)i * DMODEL);
    }

#pragma unroll
    for (int r = 0; r < 16; r++) {
        double a0e, a1e;
        double a0o = 0.0, a1o = 0.0;
        if (needx) {
            const double2 cx = nx[r & 3];
            if (r + 4 < 16)
                nx[r & 3] = *(const double2*)(xrow + (size_t)(r + 4) * DMODEL);
            a0e = mul2(cx.x, dd0);
            a1e = mul2(cx.y, dd1);
        } else {
            a0e = 0.0; a1e = 0.0;
        }
#pragma unroll
        for (int q = 0; q < 4; q++) {
            const double2 h2a = *(const double2*)&hd[r][4 * q];
            const double2 h2b = *(const double2*)&hd[r][4 * q + 2];
            a0e = fma2(h2a.x, cd0[4 * q], a0e);
            a1e = fma2(h2a.x, cd1[4 * q], a1e);
            a0o = fma2(h2a.y, cd0[4 * q + 1], a0o);
            a1o = fma2(h2a.y, cd1[4 * q + 1], a1o);
            a0e = fma2(h2b.x, cd0[4 * q + 2], a0e);
            a1e = fma2(h2b.x, cd1[4 * q + 2], a1e);
            a0o = fma2(h2b.y, cd0[4 * q + 3], a0o);
            a1o = fma2(h2b.y, cd1[4 * q + 3], a1o);
        }
        stcs2(yrow + (size_t)r * DMODEL, add2(a0e, a0o), add2(a1e, a1o));
    }
}

extern "C" void kernel_launch(void* const* d_in, const int* in_sizes, int n_in,
                              void* d_out, int out_size) {
    const float* x    = (const float*)d_in[0];   // [4,4096,1024]
    const float* A    = (const float*)d_in[1];   // [1,16]
    const float* B_in = (const float*)d_in[2];   // [1024,16]
    const float* C    = (const float*)d_in[3];   // [16,1024]
    const float* D    = (const float*)d_in[4];   // [1024]
    float* y = (float*)d_out;                    // [4,4096,1024]

    bx_kernel<<<512, 128>>>(x, A, B_in);
    chunkscan_kernel<<<64, 256>>>();
    out_kernel<<<2048, 128>>>(x, C, D, y);
}